// round 15
// baseline (speedup 1.0000x reference)
#include <cuda_runtime.h>

// Problem constants (shapes fixed by dataset; code stays correct for any
// batch_list via the offsets kernel + generic path).
#define D_DIM   300          // embedding dim
#define DC      60           // columns per chunk (multiple of 4, divides 300)
#define DC4     (DC / 4)     // 15 float4 per row-chunk
#define NCHUNK  (D_DIM / DC) // 5
#define TR      256          // row tile (== nodes per graph in this dataset)
#define RB      16           // row-blocks
#define NT      (RB * DC4)   // 240 threads per CTA
#define KIT     (TR / RB)    // 16 rows per thread in fast path
#define MAXB    8192
#define EPSV    1e-12f

// Scratch (no cudaMalloc allowed).
__device__ int g_off[MAXB + 1];
__device__ int g_B;
__device__ int g_uni;   // 1 iff all graphs have equal node counts
__device__ int g_uval;  // that count

__device__ __forceinline__ void pdl_wait() {
    asm volatile("griddepcontrol.wait;" ::: "memory");
}
__device__ __forceinline__ void pdl_trigger() {
    asm volatile("griddepcontrol.launch_dependents;" ::: "memory");
}

// ---------------------------------------------------------------------------
// Offsets kernel: detects int32 vs int64 batch_list layout. Uniform fast path
// publishes only {flag, value, count} and triggers dependent launch early.
// General path: inclusive scan to g_off, then triggers.
// ---------------------------------------------------------------------------
__global__ void offsets_kernel(const int* __restrict__ p32, int nb, int ntot) {
    __shared__ int sh[1024];
    __shared__ int s_stride, s_carry, s_uni, s_val;
    const int tid = threadIdx.x;

    if (tid == 0) {
        int stride = 1;
        if (nb > 1) {
            int v0 = p32[0], v1 = p32[1];
            if (v1 == 0 && v0 != 0) stride = 2;   // int64 little-endian
        }
        s_stride = stride;
        s_carry = 0;
        s_uni = 1;
        s_val = p32[0];
        g_off[0] = 0;
        g_uni = 0;
    }
    __syncthreads();

    const int st = s_stride;
    int B = nb;
    if (B > MAXB) B = MAXB;
    const int B1 = (st == 2) ? (B >> 1) : B;
    const int v0 = s_val;

    int uni = 1;
    for (int i = tid; i < B1; i += 1024)
        if (p32[(size_t)i * st] != v0) uni = 0;
    if (!uni) atomicAnd(&s_uni, 0);
    __syncthreads();

    if (s_uni && (long long)B1 * v0 == ntot) {
        if (tid == 0) {
            g_B = B1;
            g_uval = v0;
            g_uni = 1;          // main kernel computes offsets arithmetically
        }
        __syncthreads();        // results visible before the trigger
        pdl_trigger();          // release the main grid early
        return;
    }

    // ---- general path: inclusive scan into g_off ----
    for (int base = 0; base < B1; base += 1024) {
        int i = base + tid;
        int v = (i < B1) ? p32[(size_t)i * st] : 0;
        sh[tid] = v;
        __syncthreads();
        #pragma unroll
        for (int o = 1; o < 1024; o <<= 1) {
            int t = (tid >= o) ? sh[tid - o] : 0;
            __syncthreads();
            sh[tid] += t;
            __syncthreads();
        }
        if (i < B1) g_off[i + 1] = s_carry + sh[tid];
        __syncthreads();
        if (tid == 0) s_carry += sh[1023];
        __syncthreads();
    }

    int Bfinal = B1;
    if (st == 2 && B1 > 0 && g_off[B1] != ntot && B > B1) {
        for (int base = B1; base < B; base += 1024) {
            int i = base + tid;
            int v = (i < B) ? p32[(size_t)i * st] : 0;
            sh[tid] = v;
            __syncthreads();
            #pragma unroll
            for (int o = 1; o < 1024; o <<= 1) {
                int t = (tid >= o) ? sh[tid - o] : 0;
                __syncthreads();
                sh[tid] += t;
                __syncthreads();
            }
            if (i < B) g_off[i + 1] = s_carry + sh[tid];
            __syncthreads();
            if (tid == 0) s_carry += sh[1023];
            __syncthreads();
        }
        Bfinal = B;
    }
    if (tid == 0) g_B = Bfinal;
    __syncthreads();
    pdl_trigger();
}

// ---------------------------------------------------------------------------
// Helpers
// ---------------------------------------------------------------------------
__device__ __forceinline__ float4 min4(float4 a, float4 b) {
    return make_float4(fminf(a.x, b.x), fminf(a.y, b.y),
                       fminf(a.z, b.z), fminf(a.w, b.w));
}
__device__ __forceinline__ float4 max4(float4 a, float4 b) {
    return make_float4(fmaxf(a.x, b.x), fmaxf(a.y, b.y),
                       fmaxf(a.z, b.z), fmaxf(a.w, b.w));
}

// ---------------------------------------------------------------------------
// Main kernel (KIT=16, 3 CTAs/SM, 2-barrier fold; asymmetric cache policy):
// one CTA per (graph, 60-col chunk). Thread (rb, j) loads rows rb+16k of
// column-quad j into registers (16 in-flight LDG.128), reduces min/max in
// flight; one barrier + 60-thread scalar fold publishes mid/inv; normalize
// from registers. Loads use default .ca (boundary-line L2 merge + keeps x
// L2-resident across graph replays); stores use .cs evict-first so the
// output stream does not displace x from L2. PDL overlaps launch with the
// offsets kernel. Single DRAM read + single DRAM write of the tensor.
// ---------------------------------------------------------------------------
__global__ void __launch_bounds__(NT, 3)
cube_norm_kernel(const float* __restrict__ x, float* __restrict__ y) {
    __shared__ float pmn_s[RB * DC];   // 3840 B
    __shared__ float pmx_s[RB * DC];   // 3840 B
    __shared__ float smid[DC];
    __shared__ float sinv[DC];

    const int tid = threadIdx.x;
    const int j   = tid % DC4;         // column quad 0..14
    const int rb  = tid / DC4;         // row block 0..15
    const int g   = blockIdx.y;
    const int c0  = blockIdx.x * DC;

    pdl_wait();                        // offsets kernel results now visible

    if (g >= g_B) return;
    int r0, nr;
    if (g_uni) {
        nr = g_uval;
        r0 = g * nr;
    } else {
        r0 = g_off[g];
        nr = g_off[g + 1] - r0;
    }
    if (nr <= 0) return;

    const float* xg = x + (size_t)r0 * D_DIM + c0 + 4 * j;
    float*       yg = y + (size_t)r0 * D_DIM + c0 + 4 * j;

    if (nr == TR) {
        // ---------------- fast register-resident path ----------------
        float4 v[KIT];
        const float* p = xg + (size_t)rb * D_DIM;
        #pragma unroll
        for (int k = 0; k < KIT; k++)
            v[k] = *(const float4*)(p + (size_t)k * RB * D_DIM);

        float4 mn = v[0], mx = v[0];
        #pragma unroll
        for (int k = 1; k < KIT; k++) {
            mn = min4(mn, v[k]);
            mx = max4(mx, v[k]);
        }
        *(float4*)&pmn_s[rb * DC + 4 * j] = mn;
        *(float4*)&pmx_s[rb * DC + 4 * j] = mx;
        __syncthreads();

        // ---- fold: 60 threads, one scalar column each (conflict-free) ----
        if (tid < DC) {
            float fmn = pmn_s[tid];
            float fmx = pmx_s[tid];
            #pragma unroll
            for (int r = 1; r < RB; r++) {
                fmn = fminf(fmn, pmn_s[r * DC + tid]);
                fmx = fmaxf(fmx, pmx_s[r * DC + tid]);
            }
            smid[tid] = (fmx + fmn) * 0.5f;
            sinv[tid] = 1.0f / fmaxf((fmx - fmn) * 0.5f, EPSV);
        }
        __syncthreads();

        const float4 mid = *(const float4*)&smid[4 * j];
        const float4 inv = *(const float4*)&sinv[4 * j];

        float* q = yg + (size_t)rb * D_DIM;
        #pragma unroll
        for (int k = 0; k < KIT; k++) {
            float4 o;
            o.x = (v[k].x - mid.x) * inv.x;
            o.y = (v[k].y - mid.y) * inv.y;
            o.z = (v[k].z - mid.z) * inv.z;
            o.w = (v[k].w - mid.w) * inv.w;
            __stcs((float4*)(q + (size_t)k * RB * D_DIM), o);
        }
    } else {
        // ---------------- generic two-sweep path (not hit by dataset) ------
        float4 mn = make_float4( 3.402823466e38f,  3.402823466e38f,
                                 3.402823466e38f,  3.402823466e38f);
        float4 mx = make_float4(-3.402823466e38f, -3.402823466e38f,
                                -3.402823466e38f, -3.402823466e38f);
        for (int r = rb; r < nr; r += RB) {
            float4 a = *(const float4*)(xg + (size_t)r * D_DIM);
            mn = min4(mn, a);
            mx = max4(mx, a);
        }
        *(float4*)&pmn_s[rb * DC + 4 * j] = mn;
        *(float4*)&pmx_s[rb * DC + 4 * j] = mx;
        __syncthreads();
        if (tid < DC) {
            float fmn = pmn_s[tid];
            float fmx = pmx_s[tid];
            #pragma unroll
            for (int r = 1; r < RB; r++) {
                fmn = fminf(fmn, pmn_s[r * DC + tid]);
                fmx = fmaxf(fmx, pmx_s[r * DC + tid]);
            }
            smid[tid] = (fmx + fmn) * 0.5f;
            sinv[tid] = 1.0f / fmaxf((fmx - fmn) * 0.5f, EPSV);
        }
        __syncthreads();
        const float4 mid = *(const float4*)&smid[4 * j];
        const float4 inv = *(const float4*)&sinv[4 * j];
        for (int r = rb; r < nr; r += RB) {
            float4 a = *(const float4*)(xg + (size_t)r * D_DIM);
            float4 o;
            o.x = (a.x - mid.x) * inv.x;
            o.y = (a.y - mid.y) * inv.y;
            o.z = (a.z - mid.z) * inv.z;
            o.w = (a.w - mid.w) * inv.w;
            __stcs((float4*)(yg + (size_t)r * D_DIM), o);
        }
    }
}

// ---------------------------------------------------------------------------
extern "C" void kernel_launch(void* const* d_in, const int* in_sizes, int n_in,
                              void* d_out, int out_size) {
    const float* x  = (const float*)d_in[0];
    const int*   bl = (const int*)d_in[1];
    float*       y  = (float*)d_out;

    const int nb   = in_sizes[1];
    const int ntot = in_sizes[0] / D_DIM;

    offsets_kernel<<<1, 1024>>>(bl, nb, ntot);

    int gy = nb < MAXB ? nb : MAXB;
    if (gy < 1) gy = 1;

    // PDL: let the main kernel launch/prelude overlap the offsets kernel.
    cudaLaunchConfig_t cfg = {};
    cfg.gridDim  = dim3(NCHUNK, gy);
    cfg.blockDim = dim3(NT);
    cfg.dynamicSmemBytes = 0;
    cfg.stream = 0;
    cudaLaunchAttribute attrs[1];
    attrs[0].id = cudaLaunchAttributeProgrammaticStreamSerialization;
    attrs[0].val.programmaticStreamSerializationAllowed = 1;
    cfg.attrs = attrs;
    cfg.numAttrs = 1;
    cudaLaunchKernelEx(&cfg, cube_norm_kernel, x, y);
}

// round 16
// speedup vs baseline: 1.0101x; 1.0101x over previous
#include <cuda_runtime.h>

// Problem constants (shapes fixed by dataset; code stays correct for any
// batch_list via in-kernel verification + generic fallback path).
#define D_DIM   300          // embedding dim
#define DC      60           // columns per chunk (multiple of 4, divides 300)
#define DC4     (DC / 4)     // 15 float4 per row-chunk
#define NCHUNK  (D_DIM / DC) // 5
#define TR      256          // rows per graph (fast path)
#define RB      16           // row-blocks
#define NT      (RB * DC4)   // 240 threads per CTA
#define KIT     (TR / RB)    // 16 rows per thread in fast path
#define MAXB    8192
#define EPSV    1e-12f

// ---------------------------------------------------------------------------
// Helpers
// ---------------------------------------------------------------------------
__device__ __forceinline__ float4 min4(float4 a, float4 b) {
    return make_float4(fminf(a.x, b.x), fminf(a.y, b.y),
                       fminf(a.z, b.z), fminf(a.w, b.w));
}
__device__ __forceinline__ float4 max4(float4 a, float4 b) {
    return make_float4(fmaxf(a.x, b.x), fmaxf(a.y, b.y),
                       fmaxf(a.z, b.z), fmaxf(a.w, b.w));
}

// ---------------------------------------------------------------------------
// Fused kernel: ONE launch. Each CTA handles (graph g = blockIdx.y,
// 60-col chunk = blockIdx.x). Per CTA:
//   1. Read bl[0], bl[1]: detect int32 vs int64 (little-endian high word 0)
//      and resolve the nb convention (elements vs words) via total==ntot.
//   2. SPECULATE: if bl[0]==256 and (g+1)*256 <= ntot (bounds-safe), issue
//      all 16 LDG.128 data loads immediately with r0 = g*256.
//   3. While loads are in flight, verify uniformity of bl[0..B) (L2-hot
//      broadcast, ~5 coalesced loads/thread) and B*v0==ntot, combined
//      across the CTA with __syncthreads_and -> ~zero-cost verification.
//   4. Verified: proceed from registers (min/max reduced in flight,
//      one barrier + 60-thread scalar fold, normalize, .cs stores).
//      Not verified: per-CTA r0 via shared atomic prefix sum, generic
//      two-sweep gmem path.
// Core = R15 fast path (KIT=16, 3 CTAs/SM, 2-barrier fold, .ca loads /
// .cs stores). Single DRAM read + single DRAM write of the tensor.
// ---------------------------------------------------------------------------
__global__ void __launch_bounds__(NT, 3)
cube_norm_kernel(const float* __restrict__ x, float* __restrict__ y,
                 const int* __restrict__ bl, int nb, int ntot) {
    __shared__ float pmn_s[RB * DC];   // 3840 B
    __shared__ float pmx_s[RB * DC];   // 3840 B
    __shared__ float smid[DC];
    __shared__ float sinv[DC];
    __shared__ unsigned long long s_sum;

    const int tid = threadIdx.x;
    const int j   = tid % DC4;         // column quad 0..14
    const int rb  = tid / DC4;         // row block 0..15
    const int g   = blockIdx.y;
    const int c0  = blockIdx.x * DC;

    // ---- 1. layout detection ----
    const int b0 = __ldg(bl);
    const int b1 = (nb > 1) ? __ldg(bl + 1) : 1;
    const int st = (b1 == 0 && b0 != 0) ? 2 : 1;  // int64 little-endian
    int B = (st == 2) ? (nb >> 1) : nb;           // words convention
    if (st == 2 && (long long)B * b0 != (long long)ntot)
        B = nb;                                   // elements convention
    if (g >= B) return;

    // ---- 2. speculative fast-path loads (bounds-safe) ----
    const bool spec = (b0 == TR) &&
                      ((long long)(g + 1) * TR <= (long long)ntot);
    const float* xg_f = x + ((size_t)g * TR) * D_DIM + c0 + 4 * j;
    float*       yg_f = y + ((size_t)g * TR) * D_DIM + c0 + 4 * j;

    float4 v[KIT];
    if (spec) {
        const float* p = xg_f + (size_t)rb * D_DIM;
        #pragma unroll
        for (int k = 0; k < KIT; k++)
            v[k] = *(const float4*)(p + (size_t)k * RB * D_DIM);
    }

    // ---- 3. verify uniformity while loads are in flight ----
    int myok = 1;
    for (int i = tid; i < B; i += NT)
        myok &= (__ldg(bl + (size_t)i * st) == b0);
    const int ok = __syncthreads_and(myok &&
                                     ((long long)B * b0 == (long long)ntot));

    if (spec && ok) {
        // ---------------- fast register-resident path ----------------
        float4 mn = v[0], mx = v[0];
        #pragma unroll
        for (int k = 1; k < KIT; k++) {
            mn = min4(mn, v[k]);
            mx = max4(mx, v[k]);
        }
        *(float4*)&pmn_s[rb * DC + 4 * j] = mn;
        *(float4*)&pmx_s[rb * DC + 4 * j] = mx;
        __syncthreads();

        // fold: 60 threads, one scalar column each (conflict-free)
        if (tid < DC) {
            float fmn = pmn_s[tid];
            float fmx = pmx_s[tid];
            #pragma unroll
            for (int r = 1; r < RB; r++) {
                fmn = fminf(fmn, pmn_s[r * DC + tid]);
                fmx = fmaxf(fmx, pmx_s[r * DC + tid]);
            }
            smid[tid] = (fmx + fmn) * 0.5f;
            sinv[tid] = 1.0f / fmaxf((fmx - fmn) * 0.5f, EPSV);
        }
        __syncthreads();

        const float4 mid = *(const float4*)&smid[4 * j];
        const float4 inv = *(const float4*)&sinv[4 * j];

        float* q = yg_f + (size_t)rb * D_DIM;
        #pragma unroll
        for (int k = 0; k < KIT; k++) {
            float4 o;
            o.x = (v[k].x - mid.x) * inv.x;
            o.y = (v[k].y - mid.y) * inv.y;
            o.z = (v[k].z - mid.z) * inv.z;
            o.w = (v[k].w - mid.w) * inv.w;
            __stcs((float4*)(q + (size_t)k * RB * D_DIM), o);
        }
        return;
    }

    // ---------------- generic path (not hit by dataset) ----------------
    int r0, nr;
    if (ok) {
        r0 = g * b0;
        nr = b0;
    } else {
        if (tid == 0) s_sum = 0ull;
        __syncthreads();
        unsigned long long part = 0;
        for (int i = tid; i < g; i += NT)
            part += (unsigned long long)(unsigned)__ldg(bl + (size_t)i * st);
        if (part) atomicAdd(&s_sum, part);
        __syncthreads();
        r0 = (int)s_sum;
        nr = __ldg(bl + (size_t)g * st);
    }
    if (nr <= 0) return;

    const float* xg = x + (size_t)r0 * D_DIM + c0 + 4 * j;
    float*       yg = y + (size_t)r0 * D_DIM + c0 + 4 * j;

    float4 mn = make_float4( 3.402823466e38f,  3.402823466e38f,
                             3.402823466e38f,  3.402823466e38f);
    float4 mx = make_float4(-3.402823466e38f, -3.402823466e38f,
                            -3.402823466e38f, -3.402823466e38f);
    for (int r = rb; r < nr; r += RB) {
        float4 a = *(const float4*)(xg + (size_t)r * D_DIM);
        mn = min4(mn, a);
        mx = max4(mx, a);
    }
    *(float4*)&pmn_s[rb * DC + 4 * j] = mn;
    *(float4*)&pmx_s[rb * DC + 4 * j] = mx;
    __syncthreads();
    if (tid < DC) {
        float fmn = pmn_s[tid];
        float fmx = pmx_s[tid];
        #pragma unroll
        for (int r = 1; r < RB; r++) {
            fmn = fminf(fmn, pmn_s[r * DC + tid]);
            fmx = fmaxf(fmx, pmx_s[r * DC + tid]);
        }
        smid[tid] = (fmx + fmn) * 0.5f;
        sinv[tid] = 1.0f / fmaxf((fmx - fmn) * 0.5f, EPSV);
    }
    __syncthreads();
    const float4 mid = *(const float4*)&smid[4 * j];
    const float4 inv = *(const float4*)&sinv[4 * j];
    for (int r = rb; r < nr; r += RB) {
        float4 a = *(const float4*)(xg + (size_t)r * D_DIM);
        float4 o;
        o.x = (a.x - mid.x) * inv.x;
        o.y = (a.y - mid.y) * inv.y;
        o.z = (a.z - mid.z) * inv.z;
        o.w = (a.w - mid.w) * inv.w;
        __stcs((float4*)(yg + (size_t)r * D_DIM), o);
    }
}

// ---------------------------------------------------------------------------
extern "C" void kernel_launch(void* const* d_in, const int* in_sizes, int n_in,
                              void* d_out, int out_size) {
    const float* x  = (const float*)d_in[0];
    const int*   bl = (const int*)d_in[1];
    float*       y  = (float*)d_out;

    const int nb   = in_sizes[1];
    const int ntot = in_sizes[0] / D_DIM;

    int gy = nb < MAXB ? nb : MAXB;   // upper bound; CTAs exit via g >= B
    if (gy < 1) gy = 1;
    dim3 grid(NCHUNK, gy);
    cube_norm_kernel<<<grid, NT>>>(x, y, bl, nb, ntot);
}

// round 17
// speedup vs baseline: 1.0215x; 1.0113x over previous
#include <cuda_runtime.h>

// Problem constants (shapes fixed by dataset; code stays correct for any
// batch_list via in-kernel verification + generic fallback path).
#define D_DIM   300          // embedding dim
#define DC      60           // columns per chunk (multiple of 4, divides 300)
#define DC4     (DC / 4)     // 15 float4 per row-chunk
#define NCHUNK  (D_DIM / DC) // 5
#define TR      256          // rows per graph (fast path)
#define RB      16           // row-blocks
#define NT      (RB * DC4)   // 240 threads per CTA
#define KIT     (TR / RB)    // 16 rows per thread in fast path
#define MAXB    8192
#define EPSV    1e-12f

// ---------------------------------------------------------------------------
// Helpers
// ---------------------------------------------------------------------------
__device__ __forceinline__ float4 min4(float4 a, float4 b) {
    return make_float4(fminf(a.x, b.x), fminf(a.y, b.y),
                       fminf(a.z, b.z), fminf(a.w, b.w));
}
__device__ __forceinline__ float4 max4(float4 a, float4 b) {
    return make_float4(fmaxf(a.x, b.x), fmaxf(a.y, b.y),
                       fmaxf(a.z, b.z), fmaxf(a.w, b.w));
}

// ---------------------------------------------------------------------------
// Fused kernel: ONE launch. Each CTA handles (graph g = blockIdx.y,
// 60-col chunk = blockIdx.x). Per CTA:
//   1. Read bl[0], bl[1]: detect int32 vs int64 (little-endian high word 0)
//      and resolve the nb convention (elements vs words) via total==ntot.
//   2. SPECULATE: if bl[0]==256 and (g+1)*256 <= ntot (bounds-safe), issue
//      all 16 LDG.128 data loads immediately with r0 = g*256.
//   3. While loads are in flight, verify ONLY the prefix bl[0..g] == 256
//      (that is all r0 = g*256 needs); compute partial min/max from the
//      speculative registers and write them to smem BEFORE the verdict.
//   4. ONE __syncthreads_and publishes both the partials and the ok flag
//      (fast path keeps exactly 2 barriers). ok -> fold + normalize + .cs
//      stores. !ok (CTA-uniform) -> generic path recomputes everything.
// Core = R15 fast path (KIT=16, 3 CTAs/SM, 2-barrier fold, .ca loads /
// .cs stores). Single DRAM read + single DRAM write of the tensor.
// ---------------------------------------------------------------------------
__global__ void __launch_bounds__(NT, 3)
cube_norm_kernel(const float* __restrict__ x, float* __restrict__ y,
                 const int* __restrict__ bl, int nb, int ntot) {
    __shared__ float pmn_s[RB * DC];   // 3840 B
    __shared__ float pmx_s[RB * DC];   // 3840 B
    __shared__ float smid[DC];
    __shared__ float sinv[DC];
    __shared__ unsigned long long s_sum;

    const int tid = threadIdx.x;
    const int j   = tid % DC4;         // column quad 0..14
    const int rb  = tid / DC4;         // row block 0..15
    const int g   = blockIdx.y;
    const int c0  = blockIdx.x * DC;

    // ---- 1. layout detection ----
    const int b0 = __ldg(bl);
    const int b1 = (nb > 1) ? __ldg(bl + 1) : 1;
    const int st = (b1 == 0 && b0 != 0) ? 2 : 1;  // int64 little-endian
    int B = (st == 2) ? (nb >> 1) : nb;           // words convention
    if (st == 2 && (long long)B * b0 != (long long)ntot)
        B = nb;                                   // elements convention
    if (g >= B) return;

    // ---- 2. speculative fast-path loads (bounds-safe) ----
    const bool spec = (b0 == TR) &&
                      ((long long)(g + 1) * TR <= (long long)ntot);
    const float* xg_f = x + ((size_t)g * TR) * D_DIM + c0 + 4 * j;
    float*       yg_f = y + ((size_t)g * TR) * D_DIM + c0 + 4 * j;

    float4 v[KIT];
    if (spec) {
        const float* p = xg_f + (size_t)rb * D_DIM;
        #pragma unroll
        for (int k = 0; k < KIT; k++)
            v[k] = *(const float4*)(p + (size_t)k * RB * D_DIM);
    }

    // ---- 3. verify prefix bl[0..g] while loads are in flight ----
    int myok = spec ? 1 : 0;
    if (spec)
        for (int i = tid; i <= g; i += NT)
            myok &= (__ldg(bl + (size_t)i * st) == b0);

    // partials from speculative registers, published with the same barrier
    if (spec) {
        float4 mn = v[0], mx = v[0];
        #pragma unroll
        for (int k = 1; k < KIT; k++) {
            mn = min4(mn, v[k]);
            mx = max4(mx, v[k]);
        }
        *(float4*)&pmn_s[rb * DC + 4 * j] = mn;
        *(float4*)&pmx_s[rb * DC + 4 * j] = mx;
    }

    // ---- 4. single merged barrier: partials + verdict ----
    const int ok = __syncthreads_and(myok);

    if (ok) {
        // ---------------- fast register-resident path ----------------
        // fold: 60 threads, one scalar column each (conflict-free)
        if (tid < DC) {
            float fmn = pmn_s[tid];
            float fmx = pmx_s[tid];
            #pragma unroll
            for (int r = 1; r < RB; r++) {
                fmn = fminf(fmn, pmn_s[r * DC + tid]);
                fmx = fmaxf(fmx, pmx_s[r * DC + tid]);
            }
            smid[tid] = (fmx + fmn) * 0.5f;
            sinv[tid] = 1.0f / fmaxf((fmx - fmn) * 0.5f, EPSV);
        }
        __syncthreads();

        const float4 mid = *(const float4*)&smid[4 * j];
        const float4 inv = *(const float4*)&sinv[4 * j];

        float* q = yg_f + (size_t)rb * D_DIM;
        #pragma unroll
        for (int k = 0; k < KIT; k++) {
            float4 o;
            o.x = (v[k].x - mid.x) * inv.x;
            o.y = (v[k].y - mid.y) * inv.y;
            o.z = (v[k].z - mid.z) * inv.z;
            o.w = (v[k].w - mid.w) * inv.w;
            __stcs((float4*)(q + (size_t)k * RB * D_DIM), o);
        }
        return;
    }

    // ---------------- generic path (not hit by dataset) ----------------
    // r0 via shared atomic prefix sum over bl[0..g)
    int r0, nr;
    {
        if (tid == 0) s_sum = 0ull;
        __syncthreads();
        unsigned long long part = 0;
        for (int i = tid; i < g; i += NT)
            part += (unsigned long long)(unsigned)__ldg(bl + (size_t)i * st);
        if (part) atomicAdd(&s_sum, part);
        __syncthreads();
        r0 = (int)s_sum;
        nr = __ldg(bl + (size_t)g * st);
    }
    if (nr <= 0) return;
    __syncthreads();   // everyone past the s_sum reads before partial rewrite

    const float* xg = x + (size_t)r0 * D_DIM + c0 + 4 * j;
    float*       yg = y + (size_t)r0 * D_DIM + c0 + 4 * j;

    float4 mn = make_float4( 3.402823466e38f,  3.402823466e38f,
                             3.402823466e38f,  3.402823466e38f);
    float4 mx = make_float4(-3.402823466e38f, -3.402823466e38f,
                            -3.402823466e38f, -3.402823466e38f);
    for (int r = rb; r < nr; r += RB) {
        float4 a = *(const float4*)(xg + (size_t)r * D_DIM);
        mn = min4(mn, a);
        mx = max4(mx, a);
    }
    *(float4*)&pmn_s[rb * DC + 4 * j] = mn;
    *(float4*)&pmx_s[rb * DC + 4 * j] = mx;
    __syncthreads();
    if (tid < DC) {
        float fmn = pmn_s[tid];
        float fmx = pmx_s[tid];
        #pragma unroll
        for (int r = 1; r < RB; r++) {
            fmn = fminf(fmn, pmn_s[r * DC + tid]);
            fmx = fmaxf(fmx, pmx_s[r * DC + tid]);
        }
        smid[tid] = (fmx + fmn) * 0.5f;
        sinv[tid] = 1.0f / fmaxf((fmx - fmn) * 0.5f, EPSV);
    }
    __syncthreads();
    const float4 mid = *(const float4*)&smid[4 * j];
    const float4 inv = *(const float4*)&sinv[4 * j];
    for (int r = rb; r < nr; r += RB) {
        float4 a = *(const float4*)(xg + (size_t)r * D_DIM);
        float4 o;
        o.x = (a.x - mid.x) * inv.x;
        o.y = (a.y - mid.y) * inv.y;
        o.z = (a.z - mid.z) * inv.z;
        o.w = (a.w - mid.w) * inv.w;
        __stcs((float4*)(yg + (size_t)r * D_DIM), o);
    }
}

// ---------------------------------------------------------------------------
extern "C" void kernel_launch(void* const* d_in, const int* in_sizes, int n_in,
                              void* d_out, int out_size) {
    const float* x  = (const float*)d_in[0];
    const int*   bl = (const int*)d_in[1];
    float*       y  = (float*)d_out;

    const int nb   = in_sizes[1];
    const int ntot = in_sizes[0] / D_DIM;

    int gy = nb < MAXB ? nb : MAXB;   // upper bound; CTAs exit via g >= B
    if (gy < 1) gy = 1;
    dim3 grid(NCHUNK, gy);
    cube_norm_kernel<<<grid, NT>>>(x, y, bl, nb, ntot);
}